// round 6
// baseline (speedup 1.0000x reference)
#include <cuda_runtime.h>
#include <cuda_bf16.h>
#include <cstdint>

typedef unsigned int u32;
typedef unsigned short u16;

#define D       64
#define K       1024
#define HW      4096
#define BLOCK   128
#define CHUNK   32
#define NCHUNKS (K / CHUNK)
#define CAPL    8
#define MAXBLK  4096

// dynamic smem layout (bytes)
#define OFF_Z    0          // fp32 z [64][128]      32768
#define OFF_CN   32768      // fp32 cn[1024]          4096
#define OFF_CAND 36864      // u16 [128][32]          8192
#define OFF_RED  45056      // fp32 [64]               256
#define SMEM_SZ  45312

__device__ float g_cnorm[K];
__device__ u32   g_cbpk[K * 32];   // bf16x2-packed codebook [code][dimpair]
__device__ float g_partials[MAXBLK];

__device__ __forceinline__ u32 bf2(float lo, float hi) {
    u32 r;
    asm("cvt.rn.bf16x2.f32 %0, %1, %2;" : "=r"(r) : "f"(hi), "f"(lo));
    return r;
}
__device__ __forceinline__ void mma16816(float c[4], const u32 a0, const u32 a1,
                                         const u32 a2, const u32 a3,
                                         const u32 b0, const u32 b1) {
    asm volatile(
        "mma.sync.aligned.m16n8k16.row.col.f32.bf16.bf16.f32 "
        "{%0,%1,%2,%3}, {%4,%5,%6,%7}, {%8,%9}, {%0,%1,%2,%3};"
        : "+f"(c[0]), "+f"(c[1]), "+f"(c[2]), "+f"(c[3])
        : "r"(a0), "r"(a1), "r"(a2), "r"(a3), "r"(b0), "r"(b1));
}

// ||c||^2 (bitwise-sequential) + bf16 packed codebook
__global__ void __launch_bounds__(64) cnorm_kernel(const float* __restrict__ cb) {
    __shared__ float sCb[64 * 65];
    const int tid = threadIdx.x;
    const float* src = cb + (size_t)blockIdx.x * 64 * D;
#pragma unroll
    for (int j = 0; j < 64; j++) {
        int idx = tid + j * 64;
        sCb[(idx >> 6) * 65 + (idx & 63)] = src[idx];
    }
    __syncthreads();
    const float* row = sCb + tid * 65;
    float s = 0.f;
#pragma unroll
    for (int d = 0; d < D; d++)
        s = __fadd_rn(s, __fmul_rn(row[d], row[d]));
    const int code = blockIdx.x * 64 + tid;
    g_cnorm[code] = s;
#pragma unroll
    for (int q = 0; q < 32; q++)
        g_cbpk[code * 32 + q] = bf2(row[2 * q], row[2 * q + 1]);
}

__global__ void __launch_bounds__(BLOCK, 4)
vq_kernel(const float* __restrict__ z,
          const float* __restrict__ cb,
          float* __restrict__ out,
          long long idxOff) {
    extern __shared__ char smem[];
    float* sZ = (float*)(smem + OFF_Z);
    float* sCn = (float*)(smem + OFF_CN);
    u16* sCand = (u16*)(smem + OFF_CAND);
    u32* sCandU = (u32*)(smem + OFF_CAND);
    float* sRed = (float*)(smem + OFF_RED);

    const int tid = threadIdx.x;
    const int w = tid >> 5;
    const int lane = tid & 31;
    const int g = lane >> 2;     // row group
    const int q = lane & 3;      // col group
    const int n = blockIdx.x * BLOCK + tid;
    const int b = n >> 12;
    const int hw = n & (HW - 1);

    // stage z (exact), znorm (bitwise sequential)
    const float* zbase = z + (size_t)b * D * HW + hw;
    float zn = 0.f;
#pragma unroll
    for (int d = 0; d < D; d++) {
        float v = zbase[(size_t)d * HW];
        sZ[d * BLOCK + tid] = v;
        zn = __fadd_rn(zn, __fmul_rn(v, v));
    }
#pragma unroll
    for (int j = 0; j < K / BLOCK; j++)
        sCn[tid + j * BLOCK] = g_cnorm[tid + j * BLOCK];
#pragma unroll
    for (int j = 0; j < 16; j++)
        sCandU[tid + j * BLOCK] = 0xFFFFFFFFu;
    __syncthreads();

    // A fragments: rows {g, g+8, g+16, g+24} of this warp's 32 points
    u32 aR[4][4][2];
#pragma unroll
    for (int i = 0; i < 4; i++) {
        const int p = 32 * w + 8 * i + g;
#pragma unroll
        for (int kt = 0; kt < 4; kt++)
#pragma unroll
            for (int h = 0; h < 2; h++) {
                const int k0 = 16 * kt + 8 * h + 2 * q;
                aR[i][kt][h] = bf2(sZ[k0 * BLOCK + p], sZ[(k0 + 1) * BLOCK + p]);
            }
    }

    // block max of cn and zn (for certified delta)
    float mx = 0.f, zm = zn;
#pragma unroll
    for (int j = 0; j < K / BLOCK; j++) mx = fmaxf(mx, sCn[tid + j * BLOCK]);
#pragma unroll
    for (int o = 16; o > 0; o >>= 1) {
        mx = fmaxf(mx, __shfl_xor_sync(0xffffffffu, mx, o));
        zm = fmaxf(zm, __shfl_xor_sync(0xffffffffu, zm, o));
    }
    if (lane == 0) { sRed[w] = mx; sRed[8 + w] = zm; }
    __syncthreads();
    mx = fmaxf(fmaxf(sRed[0], sRed[1]), fmaxf(sRed[2], sRed[3]));
    zm = fmaxf(fmaxf(sRed[8], sRed[9]), fmaxf(sRed[10], sRed[11]));

    const float delta = 0.0165f * sqrtf(zm * mx) + 1e-6f * (zm + mx + 1.0f);
    float rm[4] = {3.4e38f, 3.4e38f, 3.4e38f, 3.4e38f};
    int cnt4[4] = {0, 0, 0, 0};

    // B fragment source: direct from L2-resident packed codebook.
    // bb[nt][h] = g_cbpk[(cbase + 8nt + g)*32 + q + 8kt + 4h]
    const u32* gB = g_cbpk + g * 32 + q;

#pragma unroll 1
    for (int t = 0; t < NCHUNKS; t++) {
        const int cbase = t * CHUNK;
        const u32* gBt = gB + cbase * 32;

        float cfr[2][4][4];
#pragma unroll
        for (int mt = 0; mt < 2; mt++)
#pragma unroll
            for (int nt = 0; nt < 4; nt++)
#pragma unroll
                for (int e = 0; e < 4; e++) cfr[mt][nt][e] = 0.f;

        u32 bb0[4][2], bb1[4][2];
#pragma unroll
        for (int nt = 0; nt < 4; nt++) {
            bb0[nt][0] = __ldg(&gBt[nt * 256]);
            bb0[nt][1] = __ldg(&gBt[nt * 256 + 4]);
        }
#pragma unroll
        for (int kt = 0; kt < 4; kt++) {
            // prefetch next k-group while doing MMAs on current
            if (kt < 3) {
#pragma unroll
                for (int nt = 0; nt < 4; nt++) {
                    bb1[nt][0] = __ldg(&gBt[nt * 256 + 8 * (kt + 1)]);
                    bb1[nt][1] = __ldg(&gBt[nt * 256 + 8 * (kt + 1) + 4]);
                }
            }
#pragma unroll
            for (int mt = 0; mt < 2; mt++)
#pragma unroll
                for (int nt = 0; nt < 4; nt++)
                    mma16816(cfr[mt][nt],
                             aR[2 * mt][kt][0], aR[2 * mt + 1][kt][0],
                             aR[2 * mt][kt][1], aR[2 * mt + 1][kt][1],
                             bb0[nt][0], bb0[nt][1]);
#pragma unroll
            for (int nt = 0; nt < 4; nt++) {
                bb0[nt][0] = bb1[nt][0];
                bb0[nt][1] = bb1[nt][1];
            }
        }

        // screen in registers
        float cnv[8];
#pragma unroll
        for (int nt = 0; nt < 4; nt++) {
            cnv[2 * nt] = sCn[cbase + 8 * nt + 2 * q];
            cnv[2 * nt + 1] = sCn[cbase + 8 * nt + 2 * q + 1];
        }
#pragma unroll
        for (int mt = 0; mt < 2; mt++)
#pragma unroll
            for (int hh = 0; hh < 2; hh++) {
                const int i = 2 * mt + hh;
                const float thr = rm[i] + delta;
                const int pidx = 32 * w + 8 * i + g;
#pragma unroll
                for (int nt = 0; nt < 4; nt++)
#pragma unroll
                    for (int e = 0; e < 2; e++) {
                        float s = __fmaf_rn(-2.0f, cfr[mt][nt][2 * hh + e],
                                            cnv[2 * nt + e]);
                        if (s <= thr) {
                            if (cnt4[i] < CAPL)
                                sCand[pidx * 32 + q * CAPL + cnt4[i]] =
                                    (u16)(cbase + 8 * nt + 2 * q + e);
                            cnt4[i]++;
                        }
                        rm[i] = fminf(rm[i], s);
                    }
            }
#pragma unroll
        for (int i = 0; i < 4; i++) {
            rm[i] = fminf(rm[i], __shfl_xor_sync(0xffffffffu, rm[i], 1));
            rm[i] = fminf(rm[i], __shfl_xor_sync(0xffffffffu, rm[i], 2));
        }
    }

    // overflow markers
#pragma unroll
    for (int i = 0; i < 4; i++)
        if (cnt4[i] > CAPL) {
            const int pidx = 32 * w + 8 * i + g;
            sCand[pidx * 32 + q * CAPL + CAPL - 1] = (u16)0xFFFE;
        }
    __syncwarp();

    // bit-exact refine: sequential fma ascending d; first-min via (dist,k) lexicographic
    float best = 3.4e38f;
    int bestk = 0x7FFFFFFF;
    bool ovf = false;
#pragma unroll 1
    for (int s = 0; s < 16; s++) {
        u32 v = sCandU[tid * 16 + s];
#pragma unroll
        for (int h = 0; h < 2; h++) {
            u32 kk = (h == 0) ? (v & 0xFFFFu) : (v >> 16);
            if (kk >= 0xFFFEu) { if (kk == 0xFFFEu) ovf = true; continue; }
            const float4* crow = (const float4*)(cb + (size_t)kk * D);
            float dot = 0.f;
#pragma unroll
            for (int qd = 0; qd < 16; qd++) {
                float4 c4 = __ldg(&crow[qd]);
                dot = __fmaf_rn(sZ[(4 * qd + 0) * BLOCK + tid], c4.x, dot);
                dot = __fmaf_rn(sZ[(4 * qd + 1) * BLOCK + tid], c4.y, dot);
                dot = __fmaf_rn(sZ[(4 * qd + 2) * BLOCK + tid], c4.z, dot);
                dot = __fmaf_rn(sZ[(4 * qd + 3) * BLOCK + tid], c4.w, dot);
            }
            float dist = __fsub_rn(__fadd_rn(zn, sCn[kk]), __fmul_rn(2.0f, dot));
            if (dist < best || (dist == best && (int)kk < bestk)) {
                best = dist; bestk = (int)kk;
            }
        }
    }
    if (ovf) {
        best = 3.4e38f; bestk = 0;
#pragma unroll 1
        for (int kk = 0; kk < K; kk++) {
            const float4* crow = (const float4*)(cb + (size_t)kk * D);
            float dot = 0.f;
#pragma unroll
            for (int qd = 0; qd < 16; qd++) {
                float4 c4 = __ldg(&crow[qd]);
                dot = __fmaf_rn(sZ[(4 * qd + 0) * BLOCK + tid], c4.x, dot);
                dot = __fmaf_rn(sZ[(4 * qd + 1) * BLOCK + tid], c4.y, dot);
                dot = __fmaf_rn(sZ[(4 * qd + 2) * BLOCK + tid], c4.z, dot);
                dot = __fmaf_rn(sZ[(4 * qd + 3) * BLOCK + tid], c4.w, dot);
            }
            float dist = __fsub_rn(__fadd_rn(zn, sCn[kk]), __fmul_rn(2.0f, dot));
            if (dist < best) { best = dist; bestk = kk; }
        }
    }

    // epilogue (bitwise recipes from R3)
    const float4* qrow = (const float4*)(cb + (size_t)bestk * D);
    float* outz = out + (size_t)b * D * HW + hw;
    float sumsq = 0.f;
#pragma unroll
    for (int i = 0; i < 16; i++) {
        float4 qv = __ldg(&qrow[i]);
        float qq[4] = {qv.x, qv.y, qv.z, qv.w};
#pragma unroll
        for (int j = 0; j < 4; j++) {
            float zv = sZ[(4 * i + j) * BLOCK + tid];
            float dd = __fsub_rn(qq[j], zv);
            float ov = __fadd_rn(zv, dd);
            sumsq += __fmul_rn(dd, dd);
            outz[(size_t)(4 * i + j) * HW] = ov;
        }
    }
    if (idxOff >= 0) out[idxOff + n] = (float)bestk;

#pragma unroll
    for (int o = 16; o > 0; o >>= 1)
        sumsq += __shfl_down_sync(0xffffffffu, sumsq, o);
    __syncthreads();
    if (lane == 0) sRed[w] = sumsq;
    __syncthreads();
    if (tid == 0) {
        float tot = 0.f;
#pragma unroll
        for (int ww = 0; ww < BLOCK / 32; ww++) tot += sRed[ww];
        g_partials[blockIdx.x] = tot;
    }
}

__global__ void loss_kernel(float* __restrict__ out, int nBlocks,
                            long long lossOff, float invN) {
    __shared__ float s[512];
    int tid = threadIdx.x;
    float v = 0.f;
    for (int i = tid; i < nBlocks; i += 512) v += g_partials[i];
    s[tid] = v;
    __syncthreads();
    for (int st = 256; st > 0; st >>= 1) {
        if (tid < st) s[tid] += s[tid + st];
        __syncthreads();
    }
    if (tid == 0 && lossOff >= 0) {
        float m = __fmul_rn(s[0], invN);
        out[lossOff] = __fadd_rn(m, __fmul_rn(0.25f, m));
    }
}

extern "C" void kernel_launch(void* const* d_in, const int* in_sizes, int n_in,
                              void* d_out, int out_size) {
    const float* z = (const float*)d_in[0];
    const float* cb = (const float*)d_in[1];
    float* out = (float*)d_out;

    const int zElems = in_sizes[0];        // 8388608
    const int nPoints = zElems / D;        // 131072
    const int nBlocks = nPoints / BLOCK;   // 1024

    long long lossOff = ((long long)out_size > (long long)zElems) ? (long long)zElems : -1;
    long long idxOff  = ((long long)out_size >= (long long)zElems + 1 + nPoints)
                            ? (long long)zElems + 1 : -1;

    cudaFuncSetAttribute(vq_kernel, cudaFuncAttributeMaxDynamicSharedMemorySize,
                         SMEM_SZ);

    cnorm_kernel<<<K / 64, 64>>>(cb);
    vq_kernel<<<nBlocks, BLOCK, SMEM_SZ>>>(z, cb, out, idxOff);
    loss_kernel<<<1, 512>>>(out, nBlocks, lossOff, 1.0f / (float)zElems);
}

// round 7
// speedup vs baseline: 1.0307x; 1.0307x over previous
#include <cuda_runtime.h>
#include <cuda_bf16.h>
#include <cstdint>

typedef unsigned int u32;
typedef unsigned short u16;

#define D       64
#define K       1024
#define HW      4096
#define BLOCK   128
#define CHUNK   32
#define GROUP   128          // codes staged per sync-pair (4 chunks)
#define NGROUPS (K / GROUP)
#define CAPL    8
#define MAXBLK  4096

// dynamic smem layout (bytes)
#define OFF_Z    0          // fp32 z [64][128]      32768
#define OFF_CN   32768      // fp32 cn[1024]          4096
#define OFF_STG  36864      // bf16 group [128 codes x 128B, SW128]  16384
#define OFF_CAND 53248      // u16 [128][32]          8192
#define OFF_RED  61440      // fp32 [64]               256
#define SMEM_SZ  61696

__device__ float g_cnorm[K];
__device__ u32   g_cbpk[K * 32];   // bf16x2-packed codebook [code][dimpair]
__device__ float g_partials[MAXBLK];

__device__ __forceinline__ u32 bf2(float lo, float hi) {
    u32 r;
    asm("cvt.rn.bf16x2.f32 %0, %1, %2;" : "=r"(r) : "f"(hi), "f"(lo));
    return r;
}
__device__ __forceinline__ u32 smem_u32(const void* p) {
    u32 a;
    asm("{ .reg .u64 t; cvta.to.shared.u64 t, %1; cvt.u32.u64 %0, t; }"
        : "=r"(a) : "l"(p));
    return a;
}
__device__ __forceinline__ void mma16816(float c[4], const u32 a0, const u32 a1,
                                         const u32 a2, const u32 a3,
                                         const u32 b0, const u32 b1) {
    asm volatile(
        "mma.sync.aligned.m16n8k16.row.col.f32.bf16.bf16.f32 "
        "{%0,%1,%2,%3}, {%4,%5,%6,%7}, {%8,%9}, {%0,%1,%2,%3};"
        : "+f"(c[0]), "+f"(c[1]), "+f"(c[2]), "+f"(c[3])
        : "r"(a0), "r"(a1), "r"(a2), "r"(a3), "r"(b0), "r"(b1));
}
__device__ __forceinline__ void ldmx4(u32& r0, u32& r1, u32& r2, u32& r3,
                                      u32 addr) {
    asm volatile(
        "ldmatrix.sync.aligned.m8n8.x4.shared.b16 {%0,%1,%2,%3}, [%4];"
        : "=r"(r0), "=r"(r1), "=r"(r2), "=r"(r3) : "r"(addr));
}

// ||c||^2 (bitwise-sequential) + bf16 packed codebook
__global__ void __launch_bounds__(64) cnorm_kernel(const float* __restrict__ cb) {
    __shared__ float sCb[64 * 65];
    const int tid = threadIdx.x;
    const float* src = cb + (size_t)blockIdx.x * 64 * D;
#pragma unroll
    for (int j = 0; j < 64; j++) {
        int idx = tid + j * 64;
        sCb[(idx >> 6) * 65 + (idx & 63)] = src[idx];
    }
    __syncthreads();
    const float* row = sCb + tid * 65;
    float s = 0.f;
#pragma unroll
    for (int d = 0; d < D; d++)
        s = __fadd_rn(s, __fmul_rn(row[d], row[d]));
    const int code = blockIdx.x * 64 + tid;
    g_cnorm[code] = s;
#pragma unroll
    for (int q = 0; q < 32; q++)
        g_cbpk[code * 32 + q] = bf2(row[2 * q], row[2 * q + 1]);
}

__global__ void __launch_bounds__(BLOCK, 3)
vq_kernel(const float* __restrict__ z,
          const float* __restrict__ cb,
          float* __restrict__ out,
          long long idxOff) {
    extern __shared__ char smem[];
    float* sZ = (float*)(smem + OFF_Z);
    float* sCn = (float*)(smem + OFF_CN);
    u16* sCand = (u16*)(smem + OFF_CAND);
    u32* sCandU = (u32*)(smem + OFF_CAND);
    float* sRed = (float*)(smem + OFF_RED);
    const u32 sbStg = smem_u32(smem) + OFF_STG;

    const int tid = threadIdx.x;
    const int w = tid >> 5;
    const int lane = tid & 31;
    const int g = lane >> 2;     // row group
    const int q = lane & 3;      // col group
    const int n = blockIdx.x * BLOCK + tid;
    const int b = n >> 12;
    const int hw = n & (HW - 1);

    // stage z (exact), znorm (bitwise sequential)
    const float* zbase = z + (size_t)b * D * HW + hw;
    float zn = 0.f;
#pragma unroll
    for (int d = 0; d < D; d++) {
        float v = zbase[(size_t)d * HW];
        sZ[d * BLOCK + tid] = v;
        zn = __fadd_rn(zn, __fmul_rn(v, v));
    }
#pragma unroll
    for (int j = 0; j < K / BLOCK; j++)
        sCn[tid + j * BLOCK] = g_cnorm[tid + j * BLOCK];
#pragma unroll
    for (int j = 0; j < 16; j++)
        sCandU[tid + j * BLOCK] = 0xFFFFFFFFu;
    __syncthreads();

    // A fragments: rows {g, g+8, g+16, g+24} of this warp's 32 points
    u32 aR[4][4][2];
#pragma unroll
    for (int i = 0; i < 4; i++) {
        const int p = 32 * w + 8 * i + g;
#pragma unroll
        for (int kt = 0; kt < 4; kt++)
#pragma unroll
            for (int h = 0; h < 2; h++) {
                const int k0 = 16 * kt + 8 * h + 2 * q;
                aR[i][kt][h] = bf2(sZ[k0 * BLOCK + p], sZ[(k0 + 1) * BLOCK + p]);
            }
    }

    // block max of cn and zn (for certified delta)
    float mx = 0.f, zm = zn;
#pragma unroll
    for (int j = 0; j < K / BLOCK; j++) mx = fmaxf(mx, sCn[tid + j * BLOCK]);
#pragma unroll
    for (int o = 16; o > 0; o >>= 1) {
        mx = fmaxf(mx, __shfl_xor_sync(0xffffffffu, mx, o));
        zm = fmaxf(zm, __shfl_xor_sync(0xffffffffu, zm, o));
    }
    if (lane == 0) { sRed[w] = mx; sRed[8 + w] = zm; }
    __syncthreads();
    mx = fmaxf(fmaxf(sRed[0], sRed[1]), fmaxf(sRed[2], sRed[3]));
    zm = fmaxf(fmaxf(sRed[8], sRed[9]), fmaxf(sRed[10], sRed[11]));

    const float delta = 0.0165f * sqrtf(zm * mx) + 1e-6f * (zm + mx + 1.0f);
    float rm[4] = {3.4e38f, 3.4e38f, 3.4e38f, 3.4e38f};
    int cnt4[4] = {0, 0, 0, 0};

    // ldmatrix row base for this lane: matrix sel m = lane>>3 -> (nt_off, h)
    const int mSel = lane >> 3;
    const int ntOff = mSel >> 1;
    const int hSel = mSel & 1;
    const int rowIn = lane & 7;

#pragma unroll 1
    for (int grp = 0; grp < NGROUPS; grp++) {
        __syncthreads();   // previous group's reads done before overwrite
        // stage GROUP codes, coalesced LDG -> SW128-swizzled STS
        const u32* gsrc = g_cbpk + (size_t)grp * GROUP * 32;
#pragma unroll
        for (int i = 0; i < 32; i++) {
            int idx = tid + 128 * i;
            u32 off = (u32)idx << 2;
            u32 sw = off ^ ((off >> 3) & 0x70);
            *(u32*)(smem + OFF_STG + sw) = gsrc[idx];
        }
        __syncthreads();

#pragma unroll 1
        for (int c = 0; c < GROUP / CHUNK; c++) {
            const int cbase = grp * GROUP + c * CHUNK;
            const int lbase = c * CHUNK;

            float cfr[2][4][4];
#pragma unroll
            for (int mt = 0; mt < 2; mt++)
#pragma unroll
                for (int nt = 0; nt < 4; nt++)
#pragma unroll
                    for (int e = 0; e < 4; e++) cfr[mt][nt][e] = 0.f;

#pragma unroll
            for (int kt = 0; kt < 4; kt++) {
                u32 bb[4][2];
#pragma unroll
                for (int np = 0; np < 2; np++) {   // nt pairs {0,1},{2,3}
                    const int code = lbase + 8 * (2 * np + ntOff) + rowIn;
                    u32 off = (u32)(code * 128 + kt * 32 + hSel * 16);
                    u32 sw = off ^ ((off >> 3) & 0x70);
                    ldmx4(bb[2 * np][0], bb[2 * np][1],
                          bb[2 * np + 1][0], bb[2 * np + 1][1], sbStg + sw);
                }
#pragma unroll
                for (int mt = 0; mt < 2; mt++)
#pragma unroll
                    for (int nt = 0; nt < 4; nt++)
                        mma16816(cfr[mt][nt],
                                 aR[2 * mt][kt][0], aR[2 * mt + 1][kt][0],
                                 aR[2 * mt][kt][1], aR[2 * mt + 1][kt][1],
                                 bb[nt][0], bb[nt][1]);
            }

            // screen in registers (identical numerics to R5/R6)
            float cnv[8];
#pragma unroll
            for (int nt = 0; nt < 4; nt++) {
                cnv[2 * nt] = sCn[cbase + 8 * nt + 2 * q];
                cnv[2 * nt + 1] = sCn[cbase + 8 * nt + 2 * q + 1];
            }
#pragma unroll
            for (int mt = 0; mt < 2; mt++)
#pragma unroll
                for (int hh = 0; hh < 2; hh++) {
                    const int i = 2 * mt + hh;
                    const float thr = rm[i] + delta;
                    const int pidx = 32 * w + 8 * i + g;
#pragma unroll
                    for (int nt = 0; nt < 4; nt++)
#pragma unroll
                        for (int e = 0; e < 2; e++) {
                            float s = __fmaf_rn(-2.0f, cfr[mt][nt][2 * hh + e],
                                                cnv[2 * nt + e]);
                            if (s <= thr) {
                                if (cnt4[i] < CAPL)
                                    sCand[pidx * 32 + q * CAPL + cnt4[i]] =
                                        (u16)(cbase + 8 * nt + 2 * q + e);
                                cnt4[i]++;
                            }
                            rm[i] = fminf(rm[i], s);
                        }
                }
#pragma unroll
            for (int i = 0; i < 4; i++) {
                rm[i] = fminf(rm[i], __shfl_xor_sync(0xffffffffu, rm[i], 1));
                rm[i] = fminf(rm[i], __shfl_xor_sync(0xffffffffu, rm[i], 2));
            }
        }
    }

    // overflow markers
#pragma unroll
    for (int i = 0; i < 4; i++)
        if (cnt4[i] > CAPL) {
            const int pidx = 32 * w + 8 * i + g;
            sCand[pidx * 32 + q * CAPL + CAPL - 1] = (u16)0xFFFE;
        }
    __syncwarp();

    // bit-exact refine: sequential fma ascending d; first-min via (dist,k)
    float best = 3.4e38f;
    int bestk = 0x7FFFFFFF;
    bool ovf = false;
#pragma unroll 1
    for (int s = 0; s < 16; s++) {
        u32 v = sCandU[tid * 16 + s];
#pragma unroll
        for (int h = 0; h < 2; h++) {
            u32 kk = (h == 0) ? (v & 0xFFFFu) : (v >> 16);
            if (kk >= 0xFFFEu) { if (kk == 0xFFFEu) ovf = true; continue; }
            const float4* crow = (const float4*)(cb + (size_t)kk * D);
            float dot = 0.f;
#pragma unroll
            for (int qd = 0; qd < 16; qd++) {
                float4 c4 = __ldg(&crow[qd]);
                dot = __fmaf_rn(sZ[(4 * qd + 0) * BLOCK + tid], c4.x, dot);
                dot = __fmaf_rn(sZ[(4 * qd + 1) * BLOCK + tid], c4.y, dot);
                dot = __fmaf_rn(sZ[(4 * qd + 2) * BLOCK + tid], c4.z, dot);
                dot = __fmaf_rn(sZ[(4 * qd + 3) * BLOCK + tid], c4.w, dot);
            }
            float dist = __fsub_rn(__fadd_rn(zn, sCn[kk]), __fmul_rn(2.0f, dot));
            if (dist < best || (dist == best && (int)kk < bestk)) {
                best = dist; bestk = (int)kk;
            }
        }
    }
    if (ovf) {
        best = 3.4e38f; bestk = 0;
#pragma unroll 1
        for (int kk = 0; kk < K; kk++) {
            const float4* crow = (const float4*)(cb + (size_t)kk * D);
            float dot = 0.f;
#pragma unroll
            for (int qd = 0; qd < 16; qd++) {
                float4 c4 = __ldg(&crow[qd]);
                dot = __fmaf_rn(sZ[(4 * qd + 0) * BLOCK + tid], c4.x, dot);
                dot = __fmaf_rn(sZ[(4 * qd + 1) * BLOCK + tid], c4.y, dot);
                dot = __fmaf_rn(sZ[(4 * qd + 2) * BLOCK + tid], c4.z, dot);
                dot = __fmaf_rn(sZ[(4 * qd + 3) * BLOCK + tid], c4.w, dot);
            }
            float dist = __fsub_rn(__fadd_rn(zn, sCn[kk]), __fmul_rn(2.0f, dot));
            if (dist < best) { best = dist; bestk = kk; }
        }
    }

    // epilogue (bitwise recipes from R3)
    const float4* qrow = (const float4*)(cb + (size_t)bestk * D);
    float* outz = out + (size_t)b * D * HW + hw;
    float sumsq = 0.f;
#pragma unroll
    for (int i = 0; i < 16; i++) {
        float4 qv = __ldg(&qrow[i]);
        float qq[4] = {qv.x, qv.y, qv.z, qv.w};
#pragma unroll
        for (int j = 0; j < 4; j++) {
            float zv = sZ[(4 * i + j) * BLOCK + tid];
            float dd = __fsub_rn(qq[j], zv);
            float ov = __fadd_rn(zv, dd);
            sumsq += __fmul_rn(dd, dd);
            outz[(size_t)(4 * i + j) * HW] = ov;
        }
    }
    if (idxOff >= 0) out[idxOff + n] = (float)bestk;

#pragma unroll
    for (int o = 16; o > 0; o >>= 1)
        sumsq += __shfl_down_sync(0xffffffffu, sumsq, o);
    __syncthreads();
    if (lane == 0) sRed[w] = sumsq;
    __syncthreads();
    if (tid == 0) {
        float tot = 0.f;
#pragma unroll
        for (int ww = 0; ww < BLOCK / 32; ww++) tot += sRed[ww];
        g_partials[blockIdx.x] = tot;
    }
}

__global__ void loss_kernel(float* __restrict__ out, int nBlocks,
                            long long lossOff, float invN) {
    __shared__ float s[512];
    int tid = threadIdx.x;
    float v = 0.f;
    for (int i = tid; i < nBlocks; i += 512) v += g_partials[i];
    s[tid] = v;
    __syncthreads();
    for (int st = 256; st > 0; st >>= 1) {
        if (tid < st) s[tid] += s[tid + st];
        __syncthreads();
    }
    if (tid == 0 && lossOff >= 0) {
        float m = __fmul_rn(s[0], invN);
        out[lossOff] = __fadd_rn(m, __fmul_rn(0.25f, m));
    }
}

extern "C" void kernel_launch(void* const* d_in, const int* in_sizes, int n_in,
                              void* d_out, int out_size) {
    const float* z = (const float*)d_in[0];
    const float* cb = (const float*)d_in[1];
    float* out = (float*)d_out;

    const int zElems = in_sizes[0];        // 8388608
    const int nPoints = zElems / D;        // 131072
    const int nBlocks = nPoints / BLOCK;   // 1024

    long long lossOff = ((long long)out_size > (long long)zElems) ? (long long)zElems : -1;
    long long idxOff  = ((long long)out_size >= (long long)zElems + 1 + nPoints)
                            ? (long long)zElems + 1 : -1;

    cudaFuncSetAttribute(vq_kernel, cudaFuncAttributeMaxDynamicSharedMemorySize,
                         SMEM_SZ);

    cnorm_kernel<<<K / 64, 64>>>(cb);
    vq_kernel<<<nBlocks, BLOCK, SMEM_SZ>>>(z, cb, out, idxOff);
    loss_kernel<<<1, 512>>>(out, nBlocks, lossOff, 1.0f / (float)zElems);
}

// round 8
// speedup vs baseline: 9.0503x; 8.7804x over previous
#include <cuda_runtime.h>
#include <cuda_bf16.h>
#include <cstdint>

typedef unsigned int u32;
typedef unsigned short u16;

#define D       64
#define K       1024
#define HW      4096
#define BLOCK   128
#define CHUNK   32
#define GROUP   128          // codes staged per sync-pair (4 chunks)
#define NGROUPS (K / GROUP)
#define CAPL    16
#define MAXBLK  4096

// dynamic smem layout (bytes)
#define OFF_Z    0          // fp32 z [64][128]      32768
#define OFF_CN   32768      // fp32 cn[1024]          4096
#define OFF_STG  36864      // bf16 group [128 codes x 128B, SW128]  16384
#define OFF_CAND 53248      // u16 [128][64]         16384
#define OFF_RED  69632      // fp32 [64]               256
#define SMEM_SZ  69888

__device__ float g_cnorm[K];
__device__ u32   g_cbpk[K * 32];   // bf16x2-packed codebook [code][dimpair]
__device__ float g_partials[MAXBLK];

__device__ __forceinline__ u32 bf2(float lo, float hi) {
    u32 r;
    asm("cvt.rn.bf16x2.f32 %0, %1, %2;" : "=r"(r) : "f"(hi), "f"(lo));
    return r;
}
__device__ __forceinline__ u32 smem_u32(const void* p) {
    u32 a;
    asm("{ .reg .u64 t; cvta.to.shared.u64 t, %1; cvt.u32.u64 %0, t; }"
        : "=r"(a) : "l"(p));
    return a;
}
__device__ __forceinline__ void mma16816(float c[4], const u32 a0, const u32 a1,
                                         const u32 a2, const u32 a3,
                                         const u32 b0, const u32 b1) {
    asm volatile(
        "mma.sync.aligned.m16n8k16.row.col.f32.bf16.bf16.f32 "
        "{%0,%1,%2,%3}, {%4,%5,%6,%7}, {%8,%9}, {%0,%1,%2,%3};"
        : "+f"(c[0]), "+f"(c[1]), "+f"(c[2]), "+f"(c[3])
        : "r"(a0), "r"(a1), "r"(a2), "r"(a3), "r"(b0), "r"(b1));
}
__device__ __forceinline__ void ldmx4(u32& r0, u32& r1, u32& r2, u32& r3,
                                      u32 addr) {
    asm volatile(
        "ldmatrix.sync.aligned.m8n8.x4.shared.b16 {%0,%1,%2,%3}, [%4];"
        : "=r"(r0), "=r"(r1), "=r"(r2), "=r"(r3) : "r"(addr));
}

// ||c||^2 (bitwise-sequential) + bf16 packed codebook
__global__ void __launch_bounds__(64) cnorm_kernel(const float* __restrict__ cb) {
    __shared__ float sCb[64 * 65];
    const int tid = threadIdx.x;
    const float* src = cb + (size_t)blockIdx.x * 64 * D;
#pragma unroll
    for (int j = 0; j < 64; j++) {
        int idx = tid + j * 64;
        sCb[(idx >> 6) * 65 + (idx & 63)] = src[idx];
    }
    __syncthreads();
    const float* row = sCb + tid * 65;
    float s = 0.f;
#pragma unroll
    for (int d = 0; d < D; d++)
        s = __fadd_rn(s, __fmul_rn(row[d], row[d]));
    const int code = blockIdx.x * 64 + tid;
    g_cnorm[code] = s;
#pragma unroll
    for (int q = 0; q < 32; q++)
        g_cbpk[code * 32 + q] = bf2(row[2 * q], row[2 * q + 1]);
}

__global__ void __launch_bounds__(BLOCK, 3)
vq_kernel(const float* __restrict__ z,
          const float* __restrict__ cb,
          float* __restrict__ out,
          long long idxOff) {
    extern __shared__ char smem[];
    float* sZ = (float*)(smem + OFF_Z);
    float* sCn = (float*)(smem + OFF_CN);
    u16* sCand = (u16*)(smem + OFF_CAND);
    u32* sCandU = (u32*)(smem + OFF_CAND);
    float* sRed = (float*)(smem + OFF_RED);
    const u32 sbStg = smem_u32(smem) + OFF_STG;

    const int tid = threadIdx.x;
    const int w = tid >> 5;
    const int lane = tid & 31;
    const int g = lane >> 2;     // row group
    const int q = lane & 3;      // col group
    const int n = blockIdx.x * BLOCK + tid;
    const int b = n >> 12;
    const int hw = n & (HW - 1);

    // stage z (exact), znorm (bitwise sequential)
    const float* zbase = z + (size_t)b * D * HW + hw;
    float zn = 0.f;
#pragma unroll
    for (int d = 0; d < D; d++) {
        float v = zbase[(size_t)d * HW];
        sZ[d * BLOCK + tid] = v;
        zn = __fadd_rn(zn, __fmul_rn(v, v));
    }
#pragma unroll
    for (int j = 0; j < K / BLOCK; j++)
        sCn[tid + j * BLOCK] = g_cnorm[tid + j * BLOCK];
#pragma unroll
    for (int j = 0; j < 32; j++)
        sCandU[tid + j * BLOCK] = 0xFFFFFFFFu;
    __syncthreads();

    // A fragments: rows {g, g+8, g+16, g+24} of this warp's 32 points
    u32 aR[4][4][2];
#pragma unroll
    for (int i = 0; i < 4; i++) {
        const int p = 32 * w + 8 * i + g;
#pragma unroll
        for (int kt = 0; kt < 4; kt++)
#pragma unroll
            for (int h = 0; h < 2; h++) {
                const int k0 = 16 * kt + 8 * h + 2 * q;
                aR[i][kt][h] = bf2(sZ[k0 * BLOCK + p], sZ[(k0 + 1) * BLOCK + p]);
            }
    }

    // block max of cn and zn (for certified delta)
    float mx = 0.f, zm = zn;
#pragma unroll
    for (int j = 0; j < K / BLOCK; j++) mx = fmaxf(mx, sCn[tid + j * BLOCK]);
#pragma unroll
    for (int o = 16; o > 0; o >>= 1) {
        mx = fmaxf(mx, __shfl_xor_sync(0xffffffffu, mx, o));
        zm = fmaxf(zm, __shfl_xor_sync(0xffffffffu, zm, o));
    }
    if (lane == 0) { sRed[w] = mx; sRed[8 + w] = zm; }
    __syncthreads();
    mx = fmaxf(fmaxf(sRed[0], sRed[1]), fmaxf(sRed[2], sRed[3]));
    zm = fmaxf(fmaxf(sRed[8], sRed[9]), fmaxf(sRed[10], sRed[11]));

    const float delta = 0.0165f * sqrtf(zm * mx) + 1e-6f * (zm + mx + 1.0f);
    float rm[4] = {3.4e38f, 3.4e38f, 3.4e38f, 3.4e38f};
    int cnt4[4] = {0, 0, 0, 0};

    // ldmatrix row base for this lane: matrix sel m = lane>>3 -> (nt_off, h)
    const int mSel = lane >> 3;
    const int ntOff = mSel >> 1;
    const int hSel = mSel & 1;
    const int rowIn = lane & 7;

#pragma unroll 1
    for (int grp = 0; grp < NGROUPS; grp++) {
        __syncthreads();   // previous group's reads done before overwrite
        // stage GROUP codes, coalesced LDG -> SW128-swizzled STS
        const u32* gsrc = g_cbpk + (size_t)grp * GROUP * 32;
#pragma unroll
        for (int i = 0; i < 32; i++) {
            int idx = tid + 128 * i;
            u32 off = (u32)idx << 2;
            u32 sw = off ^ ((off >> 3) & 0x70);
            *(u32*)(smem + OFF_STG + sw) = gsrc[idx];
        }
        __syncthreads();

#pragma unroll 1
        for (int c = 0; c < GROUP / CHUNK; c++) {
            const int cbase = grp * GROUP + c * CHUNK;
            const int lbase = c * CHUNK;

            float cfr[2][4][4];
#pragma unroll
            for (int mt = 0; mt < 2; mt++)
#pragma unroll
                for (int nt = 0; nt < 4; nt++)
#pragma unroll
                    for (int e = 0; e < 4; e++) cfr[mt][nt][e] = 0.f;

#pragma unroll
            for (int kt = 0; kt < 4; kt++) {
                u32 bb[4][2];
#pragma unroll
                for (int np = 0; np < 2; np++) {   // nt pairs {0,1},{2,3}
                    const int code = lbase + 8 * (2 * np + ntOff) + rowIn;
                    u32 off = (u32)(code * 128 + kt * 32 + hSel * 16);
                    u32 sw = off ^ ((off >> 3) & 0x70);
                    ldmx4(bb[2 * np][0], bb[2 * np][1],
                          bb[2 * np + 1][0], bb[2 * np + 1][1], sbStg + sw);
                }
#pragma unroll
                for (int mt = 0; mt < 2; mt++)
#pragma unroll
                    for (int nt = 0; nt < 4; nt++)
                        mma16816(cfr[mt][nt],
                                 aR[2 * mt][kt][0], aR[2 * mt + 1][kt][0],
                                 aR[2 * mt][kt][1], aR[2 * mt + 1][kt][1],
                                 bb[nt][0], bb[nt][1]);
            }

            // screen in registers — R5 semantics: inline running-min threshold
            float cnv[8];
#pragma unroll
            for (int nt = 0; nt < 4; nt++) {
                cnv[2 * nt] = sCn[cbase + 8 * nt + 2 * q];
                cnv[2 * nt + 1] = sCn[cbase + 8 * nt + 2 * q + 1];
            }
#pragma unroll
            for (int mt = 0; mt < 2; mt++)
#pragma unroll
                for (int hh = 0; hh < 2; hh++) {
                    const int i = 2 * mt + hh;
                    const int pidx = 32 * w + 8 * i + g;
#pragma unroll
                    for (int nt = 0; nt < 4; nt++)
#pragma unroll
                        for (int e = 0; e < 2; e++) {
                            float s = __fmaf_rn(-2.0f, cfr[mt][nt][2 * hh + e],
                                                cnv[2 * nt + e]);
                            if (s <= rm[i] + delta) {
                                if (cnt4[i] < CAPL)
                                    sCand[pidx * 64 + q * CAPL + cnt4[i]] =
                                        (u16)(cbase + 8 * nt + 2 * q + e);
                                cnt4[i]++;
                            }
                            rm[i] = fminf(rm[i], s);
                        }
                }
#pragma unroll
            for (int i = 0; i < 4; i++) {
                rm[i] = fminf(rm[i], __shfl_xor_sync(0xffffffffu, rm[i], 1));
                rm[i] = fminf(rm[i], __shfl_xor_sync(0xffffffffu, rm[i], 2));
            }
        }
    }

    // overflow markers
#pragma unroll
    for (int i = 0; i < 4; i++)
        if (cnt4[i] > CAPL) {
            const int pidx = 32 * w + 8 * i + g;
            sCand[pidx * 64 + q * CAPL + CAPL - 1] = (u16)0xFFFE;
        }
    __syncwarp();

    // bit-exact refine: sequential fma ascending d; first-min via (dist,k)
    float best = 3.4e38f;
    int bestk = 0x7FFFFFFF;
    bool ovf = false;
#pragma unroll 1
    for (int s = 0; s < 32; s++) {
        u32 v = sCandU[tid * 32 + s];
#pragma unroll
        for (int h = 0; h < 2; h++) {
            u32 kk = (h == 0) ? (v & 0xFFFFu) : (v >> 16);
            if (kk >= 0xFFFEu) { if (kk == 0xFFFEu) ovf = true; continue; }
            const float4* crow = (const float4*)(cb + (size_t)kk * D);
            float dot = 0.f;
#pragma unroll
            for (int qd = 0; qd < 16; qd++) {
                float4 c4 = __ldg(&crow[qd]);
                dot = __fmaf_rn(sZ[(4 * qd + 0) * BLOCK + tid], c4.x, dot);
                dot = __fmaf_rn(sZ[(4 * qd + 1) * BLOCK + tid], c4.y, dot);
                dot = __fmaf_rn(sZ[(4 * qd + 2) * BLOCK + tid], c4.z, dot);
                dot = __fmaf_rn(sZ[(4 * qd + 3) * BLOCK + tid], c4.w, dot);
            }
            float dist = __fsub_rn(__fadd_rn(zn, sCn[kk]), __fmul_rn(2.0f, dot));
            if (dist < best || (dist == best && (int)kk < bestk)) {
                best = dist; bestk = (int)kk;
            }
        }
    }
    if (ovf) {
        best = 3.4e38f; bestk = 0;
#pragma unroll 1
        for (int kk = 0; kk < K; kk++) {
            const float4* crow = (const float4*)(cb + (size_t)kk * D);
            float dot = 0.f;
#pragma unroll
            for (int qd = 0; qd < 16; qd++) {
                float4 c4 = __ldg(&crow[qd]);
                dot = __fmaf_rn(sZ[(4 * qd + 0) * BLOCK + tid], c4.x, dot);
                dot = __fmaf_rn(sZ[(4 * qd + 1) * BLOCK + tid], c4.y, dot);
                dot = __fmaf_rn(sZ[(4 * qd + 2) * BLOCK + tid], c4.z, dot);
                dot = __fmaf_rn(sZ[(4 * qd + 3) * BLOCK + tid], c4.w, dot);
            }
            float dist = __fsub_rn(__fadd_rn(zn, sCn[kk]), __fmul_rn(2.0f, dot));
            if (dist < best) { best = dist; bestk = kk; }
        }
    }

    // epilogue (bitwise recipes from R3)
    const float4* qrow = (const float4*)(cb + (size_t)bestk * D);
    float* outz = out + (size_t)b * D * HW + hw;
    float sumsq = 0.f;
#pragma unroll
    for (int i = 0; i < 16; i++) {
        float4 qv = __ldg(&qrow[i]);
        float qq[4] = {qv.x, qv.y, qv.z, qv.w};
#pragma unroll
        for (int j = 0; j < 4; j++) {
            float zv = sZ[(4 * i + j) * BLOCK + tid];
            float dd = __fsub_rn(qq[j], zv);
            float ov = __fadd_rn(zv, dd);
            sumsq += __fmul_rn(dd, dd);
            outz[(size_t)(4 * i + j) * HW] = ov;
        }
    }
    if (idxOff >= 0) out[idxOff + n] = (float)bestk;

#pragma unroll
    for (int o = 16; o > 0; o >>= 1)
        sumsq += __shfl_down_sync(0xffffffffu, sumsq, o);
    __syncthreads();
    if (lane == 0) sRed[w] = sumsq;
    __syncthreads();
    if (tid == 0) {
        float tot = 0.f;
#pragma unroll
        for (int ww = 0; ww < BLOCK / 32; ww++) tot += sRed[ww];
        g_partials[blockIdx.x] = tot;
    }
}

__global__ void loss_kernel(float* __restrict__ out, int nBlocks,
                            long long lossOff, float invN) {
    __shared__ float s[512];
    int tid = threadIdx.x;
    float v = 0.f;
    for (int i = tid; i < nBlocks; i += 512) v += g_partials[i];
    s[tid] = v;
    __syncthreads();
    for (int st = 256; st > 0; st >>= 1) {
        if (tid < st) s[tid] += s[tid + st];
        __syncthreads();
    }
    if (tid == 0 && lossOff >= 0) {
        float m = __fmul_rn(s[0], invN);
        out[lossOff] = __fadd_rn(m, __fmul_rn(0.25f, m));
    }
}

extern "C" void kernel_launch(void* const* d_in, const int* in_sizes, int n_in,
                              void* d_out, int out_size) {
    const float* z = (const float*)d_in[0];
    const float* cb = (const float*)d_in[1];
    float* out = (float*)d_out;

    const int zElems = in_sizes[0];        // 8388608
    const int nPoints = zElems / D;        // 131072
    const int nBlocks = nPoints / BLOCK;   // 1024

    long long lossOff = ((long long)out_size > (long long)zElems) ? (long long)zElems : -1;
    long long idxOff  = ((long long)out_size >= (long long)zElems + 1 + nPoints)
                            ? (long long)zElems + 1 : -1;

    cudaFuncSetAttribute(vq_kernel, cudaFuncAttributeMaxDynamicSharedMemorySize,
                         SMEM_SZ);

    cnorm_kernel<<<K / 64, 64>>>(cb);
    vq_kernel<<<nBlocks, BLOCK, SMEM_SZ>>>(z, cb, out, idxOff);
    loss_kernel<<<1, 512>>>(out, nBlocks, lossOff, 1.0f / (float)zElems);
}